// round 3
// baseline (speedup 1.0000x reference)
#include <cuda_runtime.h>
#include <cstdint>

#define D    512
#define NBAT 256
#define H    128
#define LDIM 64
#define NV   32000
#define G5   640          // 5*H
#define NH   (NBAT*H)     // 32768

// ---- persistent device scratch (allocation-free rule) ----
__device__ float g_hst[D * NBAT * H];     // 64 MB
__device__ float g_cst[D * NBAT * H];     // 64 MB
__device__ float g_table[(size_t)NV * G5];// 82 MB: emb@W[0:64] + b
__device__ int   g_lidx[D * NBAT];        // left-child step index, -1 = shift

__device__ __forceinline__ float sigf(float x) {
    return __fdividef(1.0f, 1.0f + __expf(-x));
}
__device__ __forceinline__ float tanhfast(float x) {
    return 1.0f - __fdividef(2.0f, __expf(2.0f * x) + 1.0f);
}

// ============================================================
// K1: g_table[v][c] = sum_k emb[v][k] * W[k][c] + b[c]
// ============================================================
__global__ __launch_bounds__(256) void k_table(const float* __restrict__ emb,
                                               const float* __restrict__ W,
                                               const float* __restrict__ bias) {
    extern __shared__ float sm[];
    float* emb_s = sm;              // [64][33] transposed, padded
    float* W_sc  = sm + 64 * 33;    // [64][160]
    const int v0 = blockIdx.x * 32;
    const int c0 = blockIdx.y * 160;
    const int tid = threadIdx.x;

    for (int idx = tid; idx < 32 * 64; idx += 256) {
        int vv = idx >> 6, k = idx & 63;
        emb_s[k * 33 + vv] = emb[(v0 + vv) * LDIM + k];
    }
    for (int idx = tid; idx < 64 * 40; idx += 256) {
        int k = idx / 40, cq = idx % 40;
        float4 w4 = *reinterpret_cast<const float4*>(&W[k * G5 + c0 + cq * 4]);
        *reinterpret_cast<float4*>(&W_sc[k * 160 + cq * 4]) = w4;
    }
    __syncthreads();

    const int vg = tid & 7;
    const int cg = tid >> 3;
    float acc[4][5];
#pragma unroll
    for (int j = 0; j < 5; j++) {
        float bj = __ldg(&bias[c0 + cg * 5 + j]);
#pragma unroll
        for (int i = 0; i < 4; i++) acc[i][j] = bj;
    }
#pragma unroll 4
    for (int k = 0; k < 64; k++) {
        float x[4], w[5];
#pragma unroll
        for (int i = 0; i < 4; i++) x[i] = emb_s[k * 33 + vg * 4 + i];
#pragma unroll
        for (int j = 0; j < 5; j++) w[j] = W_sc[k * 160 + cg * 5 + j];
#pragma unroll
        for (int i = 0; i < 4; i++)
#pragma unroll
            for (int j = 0; j < 5; j++) acc[i][j] += x[i] * w[j];
    }
#pragma unroll
    for (int i = 0; i < 4; i++)
#pragma unroll
        for (int j = 0; j < 5; j++)
            g_table[(size_t)(v0 + vg * 4 + i) * G5 + c0 + cg * 5 + j] = acc[i][j];
}

// ============================================================
// K2: stack simulation -> g_lidx[t][b] (-1 for shift)
// ============================================================
__global__ __launch_bounds__(NBAT) void k_lidx(const int* __restrict__ trans) {
    int b = threadIdx.x;
    short st[D];
    int ptr = 0;
    for (int t = 0; t < D; t++) {
        int m = trans[t * NBAT + b];
        int lx = -1;
        if (m) lx = st[ptr - 2];
        int np = ptr - 2 * m;
        st[np] = (short)t;
        ptr = np + 1;
        g_lidx[t * NBAT + b] = lx;
    }
}

// ============================================================
// Main: 16 clusters x 8 CTAs, 256 thr/CTA, 1 CTA/SM.
// Cluster owns 16 batch; CTA rank r owns h-dims [16r,16r+16)
// -> 80 gate cols; W slice DUPLICATED in SMEM for f32x2.
// SMEM: Wd[256][160] 160KB | X[2][256][20] 40KB | Gp 22.5KB | leaf 0.5KB
// ============================================================
#define XROW   20
#define XBUF   (256 * XROW)
#define GPROW  18
#define SM_WD  0
#define SM_X   (256 * 160)
#define SM_GP  (SM_X + 2 * XBUF)
#define SM_LF  (SM_GP + 4 * 16 * 5 * GPROW)
#define SM_TOT ((SM_LF + 128) * 4)

__global__ __launch_bounds__(256, 1) __cluster_dims__(8, 1, 1)
void k_main(const int* __restrict__ trans,
            const int* __restrict__ labels,
            const float* __restrict__ W,
            const float* __restrict__ leaf,
            float* __restrict__ out) {
    extern __shared__ float sm[];
    float* Wd     = sm + SM_WD;
    float* Xbuf   = sm + SM_X;
    float* Gp     = sm + SM_GP;
    float* leaf_s = sm + SM_LF;

    const int bx  = blockIdx.x;
    const int r   = bx & 7;
    const int B   = (bx >> 3) * 16;
    const int tid = threadIdx.x;
    const int r16 = r * 16;

    // roles
    const int b   = tid & 15;        // batch (assembly / nonlin / prefetch)
    const int jk  = tid >> 4;        // k-group (assembly) == owned j (nonlin)
    const int q   = tid >> 6;        // GEMM k-quarter
    const int ww  = tid & 63;
    const int bg  = ww & 3;          // GEMM batch group of 4
    const int jj  = ww >> 2;         // GEMM owned dim

    // ---- prologue ----
    for (int idx = tid; idx < 256 * 80; idx += 256) {
        int k = idx / 80, cc = idx % 80;
        float w = __ldg(&W[(64 + k) * G5 + (cc >> 4) * H + r16 + (cc & 15)]);
        Wd[idx * 2]     = w;
        Wd[idx * 2 + 1] = w;
    }
    if (tid < 128) leaf_s[tid] = leaf[tid];
    __syncthreads();

    // schedule regs: A = step t, B = step t+1 (rotated)
    int liA  = __ldg(&g_lidx[B + b]);
    int liB  = __ldg(&g_lidx[NBAT + B + b]);
    int labA = __ldg(&labels[B + b]);
    int labB = __ldg(&labels[NBAT + B + b]);

    // prefetch state for t=0
    float tab5[5];
#pragma unroll
    for (int g = 0; g < 5; g++)
        tab5[g] = __ldg(&g_table[(size_t)labA * G5 + g * H + r16 + jk]);
    float cl = (liA >= 0) ? __ldcg(&g_cst[(size_t)liA * NH + (B + b) * H + r16 + jk])
                          : leaf_s[r16 + jk];
    {   // X[0] left half (t=0)
        float xl[8];
        if (liA >= 0) {
            const float4* s4 = reinterpret_cast<const float4*>(
                &g_hst[(size_t)liA * NH + (B + b) * H + jk * 8]);
            float4 a = __ldcg(s4), c4 = __ldcg(s4 + 1);
            xl[0]=a.x; xl[1]=a.y; xl[2]=a.z; xl[3]=a.w;
            xl[4]=c4.x; xl[5]=c4.y; xl[6]=c4.z; xl[7]=c4.w;
        } else {
#pragma unroll
            for (int i = 0; i < 8; i++) xl[i] = leaf_s[jk * 8 + i];
        }
#pragma unroll
        for (int i = 0; i < 8; i++) Xbuf[(jk * 8 + i) * XROW + b] = xl[i];
    }
    float cprev = 0.0f;
    int cur = 0;

    for (int t = 0; t < D; t++) {
        float* Xc = Xbuf + cur * XBUF;
        float* Xn = Xbuf + (cur ^ 1) * XBUF;

        // ---- right half of X[cur]: h(t-1) or leaf (mask = liA>=0) ----
        float rr[8];
        if (liA >= 0) {
            const float4* s4 = reinterpret_cast<const float4*>(
                &g_hst[(size_t)(t - 1) * NH + (B + b) * H + jk * 8]);
            float4 a = __ldcg(s4), c4 = __ldcg(s4 + 1);
            rr[0]=a.x; rr[1]=a.y; rr[2]=a.z; rr[3]=a.w;
            rr[4]=c4.x; rr[5]=c4.y; rr[6]=c4.z; rr[7]=c4.w;
        } else {
#pragma unroll
            for (int i = 0; i < 8; i++) rr[i] = leaf_s[jk * 8 + i];
        }

        // ---- prefetches for t+1 (left child <= t-1: already published) ----
        float xl[8];
        if (liB >= 0) {
            const float4* s4 = reinterpret_cast<const float4*>(
                &g_hst[(size_t)liB * NH + (B + b) * H + jk * 8]);
            float4 a = __ldcg(s4), c4 = __ldcg(s4 + 1);
            xl[0]=a.x; xl[1]=a.y; xl[2]=a.z; xl[3]=a.w;
            xl[4]=c4.x; xl[5]=c4.y; xl[6]=c4.z; xl[7]=c4.w;
        } else {
#pragma unroll
            for (int i = 0; i < 8; i++) xl[i] = leaf_s[jk * 8 + i];
        }
        float cln = (liB >= 0)
            ? __ldcg(&g_cst[(size_t)liB * NH + (B + b) * H + r16 + jk])
            : leaf_s[r16 + jk];
        float t5n[5];
#pragma unroll
        for (int g = 0; g < 5; g++)
            t5n[g] = __ldg(&g_table[(size_t)labB * G5 + g * H + r16 + jk]);
        const int t2 = (t + 2 < D) ? (t + 2) : (D - 1);
        const int liC  = __ldg(&g_lidx[t2 * NBAT + B + b]);
        const int labC = __ldg(&labels[t2 * NBAT + B + b]);

#pragma unroll
        for (int i = 0; i < 8; i++) Xc[(128 + jk * 8 + i) * XROW + b] = rr[i];
        __syncthreads();   // X[cur] complete; X[nxt] free for writes

        // ---- GEMM: quarter q does k = q*64 .. q*64+63 (f32x2) ----
        unsigned long long acc[2][5];
#pragma unroll
        for (int g = 0; g < 5; g++) { acc[0][g] = 0ULL; acc[1][g] = 0ULL; }
        {
            const float* xp = Xc + q * 64 * XROW + bg * 4;
            const unsigned long long* wp =
                reinterpret_cast<const unsigned long long*>(Wd) + q * 64 * 80 + jj;
#pragma unroll 4
            for (int k = 0; k < 64; k++) {
                ulonglong2 xv = *reinterpret_cast<const ulonglong2*>(xp + k * XROW);
                const unsigned long long* wr = wp + k * 80;
#pragma unroll
                for (int g = 0; g < 5; g++) {
                    unsigned long long w2 = wr[g * 16];
                    asm("fma.rn.f32x2 %0, %1, %2, %0;"
                        : "+l"(acc[0][g]) : "l"(xv.x), "l"(w2));
                    asm("fma.rn.f32x2 %0, %1, %2, %0;"
                        : "+l"(acc[1][g]) : "l"(xv.y), "l"(w2));
                }
            }
        }

        // store prefetched left half for t+1 (hidden behind GEMM latency)
#pragma unroll
        for (int i = 0; i < 8; i++) Xn[(jk * 8 + i) * XROW + b] = xl[i];

        // partials -> Gp
#pragma unroll
        for (int g = 0; g < 5; g++) {
            int row = ((q * 16 + jj) * 5 + g) * GPROW + bg * 4;
            *reinterpret_cast<unsigned long long*>(&Gp[row])     = acc[0][g];
            *reinterpret_cast<unsigned long long*>(&Gp[row + 2]) = acc[1][g];
        }
        __syncthreads();

        // ---- reduce + nonlinearity: thread owns (b, j=jk) ----
        {
            float gate[5];
#pragma unroll
            for (int g = 0; g < 5; g++) gate[g] = tab5[g];
#pragma unroll
            for (int q2 = 0; q2 < 4; q2++)
#pragma unroll
                for (int g = 0; g < 5; g++)
                    gate[g] += Gp[((q2 * 16 + jk) * 5 + g) * GPROW + b];

            float crv = (liA >= 0) ? cprev : leaf_s[r16 + jk];
            float c = sigf(gate[0]) * tanhfast(gate[4])
                    + sigf(gate[1]) * cl + sigf(gate[2]) * crv;
            float h = sigf(gate[3]) * tanhfast(c);
            cprev = c;
            const size_t o = (size_t)t * NH + (B + b) * H + r16 + jk;
            g_hst[o] = h;
            g_cst[o] = c;
            if (t == D - 1) {
                out[(B + b) * H + r16 + jk]      = c;   // cells
                out[NH + (B + b) * H + r16 + jk] = h;   // embeddings
            }
        }

        // ---- publish step t cluster-wide ----
        asm volatile("barrier.cluster.arrive.aligned;" ::: "memory");
        asm volatile("barrier.cluster.wait.aligned;" ::: "memory");

        // rotate pipeline state
        liA = liB; liB = liC; labB = labC;
        cl = cln;
#pragma unroll
        for (int g = 0; g < 5; g++) tab5[g] = t5n[g];
        cur ^= 1;
    }
}

// ============================================================
extern "C" void kernel_launch(void* const* d_in, const int* in_sizes, int n_in,
                              void* d_out, int out_size) {
    const int*   trans  = (const int*)d_in[0];
    const int*   labels = (const int*)d_in[1];
    const float* emb    = (const float*)d_in[2];
    const float* W      = (const float*)d_in[3];
    const float* bias   = (const float*)d_in[4];
    const float* leaf   = (const float*)d_in[5];
    float* out = (float*)d_out;

    cudaFuncSetAttribute(k_table, cudaFuncAttributeMaxDynamicSharedMemorySize,
                         64 * 33 * 4 + 64 * 160 * 4);
    cudaFuncSetAttribute(k_main, cudaFuncAttributeMaxDynamicSharedMemorySize,
                         SM_TOT);

    dim3 tgrid(NV / 32, G5 / 160);
    k_table<<<tgrid, 256, 64 * 33 * 4 + 64 * 160 * 4>>>(emb, W, bias);
    k_lidx<<<1, NBAT>>>(trans);
    k_main<<<128, 256, SM_TOT>>>(trans, labels, W, leaf, out);
}